// round 3
// baseline (speedup 1.0000x reference)
#include <cuda_runtime.h>
#include <cuda_bf16.h>
#include <math.h>

#define Wd 256
#define Hd 256
#define HW 65536

typedef unsigned long long ull;

// ---------------- scratch buffers (no allocation allowed) ----------------
__device__ float g_buf_a[216 * HW];
__device__ float g_buf_b[216 * HW];
__device__ float g_off [144 * HW];
__device__ float g_mask[ 72 * HW];
__device__ float g_cat [128 * HW];

// ---------------- packed f32x2 helpers ----------------
__device__ __forceinline__ ull pack2(float lo, float hi) {
    ull r;
    asm("mov.b64 %0, {%1, %2};" : "=l"(r) : "f"(lo), "f"(hi));
    return r;
}
__device__ __forceinline__ ull fma2(ull a, ull b, ull c) {
    ull d;
    asm("fma.rn.f32x2 %0, %1, %2, %3;" : "=l"(d) : "l"(a), "l"(b), "l"(c));
    return d;
}
__device__ __forceinline__ void unpack2(ull v, float& lo, float& hi) {
    asm("mov.b64 {%0, %1}, %2;" : "=f"(lo), "=f"(hi) : "l"(v));
}

// ---------------- generic 3x3 conv, pad=1, stride=1, FFMA2 ----------------
// Block: (32,8). Spatial tile 32x32 (4 rows per thread, 2 packed row-pairs).
// OCB output channels per block (blockIdx.z selects the group).
template<int CIN, int OCB, bool LRELU>
__global__ __launch_bounds__(256)
void conv3x3_kernel(const float* __restrict__ in, const float* __restrict__ wt,
                    const float* __restrict__ bias, float* __restrict__ out)
{
    __shared__ float sin_[34 * 34];
    __shared__ ull sw2[OCB * 9];     // weights duplicated into both f32x2 lanes
    const int tx = threadIdx.x, ty = threadIdx.y;
    const int tid = ty * 32 + tx;
    const int w0 = blockIdx.x * 32;
    const int h0 = blockIdx.y * 32;
    const int ocbase = blockIdx.z * OCB;

    ull acc[OCB][2];
#pragma unroll
    for (int o = 0; o < OCB; o++) { acc[o][0] = 0ull; acc[o][1] = 0ull; }

    for (int cin = 0; cin < CIN; cin++) {
        const float* plane = in + (size_t)cin * HW;
        // load 34x34 input tile (zero-padded at image borders)
        for (int i = tid; i < 34 * 34; i += 256) {
            int r = i / 34, c = i - r * 34;
            int gh = h0 + r - 1, gw = w0 + c - 1;
            float v = 0.f;
            if ((unsigned)gh < Hd && (unsigned)gw < Wd) v = plane[gh * Wd + gw];
            sin_[i] = v;
        }
        // load OCB 3x3 filters for this cin, lane-duplicated
        for (int i = tid; i < OCB * 9; i += 256) {
            int o = i / 9, k = i - o * 9;
            float w = wt[(((size_t)(ocbase + o)) * CIN + cin) * 9 + k];
            sw2[i] = pack2(w, w);
        }
        __syncthreads();

        // packed input rows: vp[r] = (v[r], v[r+1]) for r = 0..4
        ull vp[5][3];
        const int rbase = ty * 4;
#pragma unroll
        for (int r = 0; r < 5; r++)
#pragma unroll
            for (int c = 0; c < 3; c++)
                vp[r][c] = pack2(sin_[(rbase + r) * 34 + tx + c],
                                 sin_[(rbase + r + 1) * 34 + tx + c]);

#pragma unroll
        for (int o = 0; o < OCB; o++) {
            ull a0 = acc[o][0], a1 = acc[o][1];
#pragma unroll
            for (int t = 0; t < 9; t++) {
                const int kr = t / 3, kc = t - kr * 3;
                ull kk = sw2[o * 9 + t];
                a0 = fma2(kk, vp[kr][kc], a0);       // output rows 0,1
                a1 = fma2(kk, vp[kr + 2][kc], a1);   // output rows 2,3
            }
            acc[o][0] = a0; acc[o][1] = a1;
        }
        __syncthreads();
    }

#pragma unroll
    for (int o = 0; o < OCB; o++) {
        float bv = bias[ocbase + o];
#pragma unroll
        for (int p = 0; p < 2; p++) {
            float lo, hi;
            unpack2(acc[o][p], lo, hi);
            float r0 = lo + bv, r1 = hi + bv;
            if (LRELU) {
                r0 = (r0 >= 0.f) ? r0 : 0.1f * r0;
                r1 = (r1 >= 0.f) ? r1 : 0.1f * r1;
            }
            int row = h0 + ty * 4 + p * 2;
            out[(size_t)(ocbase + o) * HW + row * Wd + (w0 + tx)] = r0;
            out[(size_t)(ocbase + o) * HW + (row + 1) * Wd + (w0 + tx)] = r1;
        }
    }
}

// ---------------- offset/mask transform ----------------
__global__ void offxform_kernel(const float* __restrict__ conv_out,
                                const float* __restrict__ flow,
                                float* __restrict__ off, float* __restrict__ mask)
{
    int idx = blockIdx.x * 256 + threadIdx.x;
    if (idx >= 216 * HW) return;
    int c = idx >> 16;          // idx / HW
    int hw = idx & (HW - 1);
    float v = conv_out[idx];
    if (c < 144) {
        float f = flow[((c & 1) ^ 1) * HW + hw];
        off[idx] = 10.0f * tanhf(v) + f;
    } else {
        mask[(c - 144) * HW + hw] = 1.0f / (1.0f + expf(-v));
    }
}

// ---------------- modulated deformable conv (FFMA2 register-tiled) ----------------
// 128 threads, 128 consecutive pixels per block. For each of 8 groups:
// sample the 72-deep (Cg=8 x K=9) columns into smem, then GEMM:
// each thread owns an 8oc x 8px tile (4 f32x2 pixel pairs per oc).
__global__ __launch_bounds__(128)
void mdcn_kernel(const float* __restrict__ x, const float* __restrict__ off,
                 const float* __restrict__ mask, const float* __restrict__ wt,
                 const float* __restrict__ bias, float* __restrict__ out)
{
    __shared__ float samp[72 * 128];
    __shared__ float wsm[64 * 73];     // padded stride 73 -> no bank conflict
    const int tid = threadIdx.x;
    const int h = blockIdx.y;
    const int col0 = blockIdx.x * 128;
    const int pix = col0 + tid;        // sampling pixel for this thread
    const int hw = h * Wd + pix;
    const int ob = (tid >> 4) * 8;     // 8 output channels per thread
    const int p0 = (tid & 15) * 8;     // 8 pixels per thread

    ull acc[8][4];
#pragma unroll
    for (int o = 0; o < 8; o++)
#pragma unroll
        for (int p = 0; p < 4; p++) acc[o][p] = 0ull;

    for (int g = 0; g < 8; g++) {
        // ---- weight slice for this group: wsm[o][ck], ck = c*9+k ----
        for (int i = tid; i < 64 * 72; i += 128) {
            int o = i / 72, ck = i - o * 72;
            int c = ck / 9, k = ck - c * 9;
            wsm[o * 73 + ck] = wt[((size_t)o * 64 + g * 8 + c) * 9 + k];
        }
        // ---- sampling phase: one pixel per thread, 9 taps x 8 channels ----
#pragma unroll
        for (int k = 0; k < 9; k++) {
            int gk = g * 9 + k;
            float offy = off[(gk * 2 + 0) * HW + hw];
            float offx = off[(gk * 2 + 1) * HW + hw];
            float m    = mask[gk * HW + hw];
            float py = (float)h   + (float)(k / 3 - 1) + offy;
            float px = (float)pix + (float)(k % 3 - 1) + offx;
            float y0f = floorf(py), x0f = floorf(px);
            float ly = py - y0f, lx = px - x0f;
            int y0 = (int)y0f, x0i = (int)x0f;
            int y1 = y0 + 1,  x1 = x0i + 1;
            bool vy0 = (unsigned)y0 < Hd, vy1 = (unsigned)y1 < Hd;
            bool vx0 = (unsigned)x0i < Wd, vx1 = (unsigned)x1 < Wd;
            int yc0 = min(max(y0, 0), Hd - 1), yc1 = min(max(y1, 0), Hd - 1);
            int xc0 = min(max(x0i, 0), Wd - 1), xc1 = min(max(x1, 0), Wd - 1);
            float w00 = (vy0 && vx0) ? (1.f - ly) * (1.f - lx) * m : 0.f;
            float w01 = (vy0 && vx1) ? (1.f - ly) * lx * m : 0.f;
            float w10 = (vy1 && vx0) ? ly * (1.f - lx) * m : 0.f;
            float w11 = (vy1 && vx1) ? ly * lx * m : 0.f;
            int i00 = yc0 * Wd + xc0, i01 = yc0 * Wd + xc1;
            int i10 = yc1 * Wd + xc0, i11 = yc1 * Wd + xc1;
#pragma unroll
            for (int c = 0; c < 8; c++) {
                const float* p = x + (size_t)(g * 8 + c) * HW;
                samp[(c * 9 + k) * 128 + tid] =
                    w00 * p[i00] + w01 * p[i01] + w10 * p[i10] + w11 * p[i11];
            }
        }
        __syncthreads();
        // ---- GEMM: acc[o][pair] += W[ob+o, ck] * samp[ck, p0 + pair*2 + {0,1}] ----
#pragma unroll 2
        for (int ck = 0; ck < 72; ck++) {
            const ulonglong2* sp = (const ulonglong2*)&samp[ck * 128 + p0];
            ulonglong2 s01 = sp[0];   // pixel pairs (p0,p0+1) and (p0+2,p0+3)
            ulonglong2 s23 = sp[1];   // pixel pairs (p0+4..p0+7)
#pragma unroll
            for (int oi = 0; oi < 8; oi++) {
                float w = wsm[(ob + oi) * 73 + ck];
                ull kk = pack2(w, w);
                acc[oi][0] = fma2(kk, s01.x, acc[oi][0]);
                acc[oi][1] = fma2(kk, s01.y, acc[oi][1]);
                acc[oi][2] = fma2(kk, s23.x, acc[oi][2]);
                acc[oi][3] = fma2(kk, s23.y, acc[oi][3]);
            }
        }
        __syncthreads();
    }

    // ---- epilogue: bias + store (float2 per pixel pair) ----
#pragma unroll
    for (int oi = 0; oi < 8; oi++) {
        float bv = bias[ob + oi];
        float* orow = out + (size_t)(ob + oi) * HW + h * Wd + col0 + p0;
#pragma unroll
        for (int p = 0; p < 4; p++) {
            float lo, hi;
            unpack2(acc[oi][p], lo, hi);
            float2 v = make_float2(lo + bv, hi + bv);
            *(float2*)(orow + p * 2) = v;
        }
    }
}

// ---------------- host orchestration ----------------
extern "C" void kernel_launch(void* const* d_in, const int* in_sizes, int n_in,
                              void* d_out, int out_size)
{
    const float* feat_prev       = (const float*)d_in[0];
    const float* feat_next       = (const float*)d_in[1];
    const float* extra_feat_prev = (const float*)d_in[2];
    const float* extra_feat_next = (const float*)d_in[3];
    const float* flow_prev       = (const float*)d_in[4];
    const float* flow_next       = (const float*)d_in[5];
    const float* off1_w[4] = {(const float*)d_in[6],  (const float*)d_in[8],
                              (const float*)d_in[10], (const float*)d_in[12]};
    const float* off1_b[4] = {(const float*)d_in[7],  (const float*)d_in[9],
                              (const float*)d_in[11], (const float*)d_in[13]};
    const float* off2_w[4] = {(const float*)d_in[14], (const float*)d_in[16],
                              (const float*)d_in[18], (const float*)d_in[20]};
    const float* off2_b[4] = {(const float*)d_in[15], (const float*)d_in[17],
                              (const float*)d_in[19], (const float*)d_in[21]};
    const float* dcn1_w = (const float*)d_in[22];
    const float* dcn1_b = (const float*)d_in[23];
    const float* dcn2_w = (const float*)d_in[24];
    const float* dcn2_b = (const float*)d_in[25];
    const float* fus_w  = (const float*)d_in[26];
    const float* fus_b  = (const float*)d_in[27];
    float* out = (float*)d_out;

    float *buf_a, *buf_b, *offp, *maskp, *catp;
    cudaGetSymbolAddress((void**)&buf_a, g_buf_a);
    cudaGetSymbolAddress((void**)&buf_b, g_buf_b);
    cudaGetSymbolAddress((void**)&offp,  g_off);
    cudaGetSymbolAddress((void**)&maskp, g_mask);
    cudaGetSymbolAddress((void**)&catp,  g_cat);

    dim3 cb(32, 8);
    dim3 cg64(8, 8, 8);    // 64 output channels, OCB=8
    dim3 cg216(8, 8, 27);  // 216 output channels, OCB=8
    dim3 mg(2, 256);       // mdcn: 2 x 128 pixels per row, 256 rows
    int nxf = (216 * HW + 255) / 256;

    // ---- branch prev ----
    conv3x3_kernel<128, 8, true ><<<cg64,  cb>>>(extra_feat_prev, off1_w[0], off1_b[0], buf_a);
    conv3x3_kernel< 64, 8, true ><<<cg64,  cb>>>(buf_a, off1_w[1], off1_b[1], buf_b);
    conv3x3_kernel< 64, 8, true ><<<cg64,  cb>>>(buf_b, off1_w[2], off1_b[2], buf_a);
    conv3x3_kernel< 64, 8, false><<<cg216, cb>>>(buf_a, off1_w[3], off1_b[3], buf_b);
    offxform_kernel<<<nxf, 256>>>(buf_b, flow_prev, offp, maskp);
    mdcn_kernel<<<mg, 128>>>(feat_prev, offp, maskp, dcn1_w, dcn1_b, catp);

    // ---- branch next ----
    conv3x3_kernel<128, 8, true ><<<cg64,  cb>>>(extra_feat_next, off2_w[0], off2_b[0], buf_a);
    conv3x3_kernel< 64, 8, true ><<<cg64,  cb>>>(buf_a, off2_w[1], off2_b[1], buf_b);
    conv3x3_kernel< 64, 8, true ><<<cg64,  cb>>>(buf_b, off2_w[2], off2_b[2], buf_a);
    conv3x3_kernel< 64, 8, false><<<cg216, cb>>>(buf_a, off2_w[3], off2_b[3], buf_b);
    offxform_kernel<<<nxf, 256>>>(buf_b, flow_next, offp, maskp);
    mdcn_kernel<<<mg, 128>>>(feat_next, offp, maskp, dcn2_w, dcn2_b, catp + (size_t)64 * HW);

    // ---- fusion conv ----
    conv3x3_kernel<128, 8, false><<<cg64, cb>>>(catp, fus_w, fus_b, out);
}

// round 4
// speedup vs baseline: 2.4069x; 2.4069x over previous
#include <cuda_runtime.h>
#include <cuda_bf16.h>
#include <math.h>

#define Wd 256
#define Hd 256
#define HW 65536

// ---------------- scratch buffers (no allocation allowed) ----------------
__device__ float g_buf_a[216 * HW];
__device__ float g_buf_b[216 * HW];
__device__ float g_off [144 * HW];
__device__ float g_mask[ 72 * HW];
__device__ float g_cat [128 * HW];

// ---------------- cp.async helpers ----------------
__device__ __forceinline__ unsigned smem_u32(const void* p) {
    return (unsigned)__cvta_generic_to_shared(p);
}
__device__ __forceinline__ void cp_async4(void* dst, const void* src, int src_bytes) {
    asm volatile("cp.async.ca.shared.global [%0], [%1], 4, %2;\n"
                 :: "r"(smem_u32(dst)), "l"(src), "r"(src_bytes) : "memory");
}
__device__ __forceinline__ void cp_commit() {
    asm volatile("cp.async.commit_group;\n" ::: "memory");
}
template<int N>
__device__ __forceinline__ void cp_wait() {
    asm volatile("cp.async.wait_group %0;\n" :: "n"(N) : "memory");
}

// ---------------- generic 3x3 conv, pad=1, stride=1 ----------------
// Block: (32,8). Spatial tile 32x32 (4 rows per thread). OCB out-channels per
// block (blockIdx.z). Input tile + weights double-buffered via cp.async.
template<int CIN, int OCB, bool LRELU>
__global__ __launch_bounds__(256)
void conv3x3_kernel(const float* __restrict__ in, const float* __restrict__ wt,
                    const float* __restrict__ bias, float* __restrict__ out)
{
    __shared__ float sin_[2][34 * 34];
    __shared__ float sw[2][OCB * 9];
    const int tx = threadIdx.x, ty = threadIdx.y;
    const int tid = ty * 32 + tx;
    const int w0 = blockIdx.x * 32;
    const int h0 = blockIdx.y * 32;
    const int ocbase = blockIdx.z * OCB;

    float acc[OCB][4];
#pragma unroll
    for (int o = 0; o < OCB; o++)
#pragma unroll
        for (int i = 0; i < 4; i++) acc[o][i] = 0.f;

    // issue async loads of input tile + weight slice for channel `cin` into buf
    auto issue_loads = [&](int cin, int buf) {
        const float* plane = in + (size_t)cin * HW;
        for (int i = tid; i < 34 * 34; i += 256) {
            int r = i / 34, c = i - r * 34;
            int gh = h0 + r - 1, gw = w0 + c - 1;
            bool v = ((unsigned)gh < Hd) && ((unsigned)gw < Wd);
            const float* g = v ? (plane + gh * Wd + gw) : plane;
            cp_async4(&sin_[buf][i], g, v ? 4 : 0);
        }
        if (tid < OCB * 9) {
            int o = tid / 9, k = tid - o * 9;
            cp_async4(&sw[buf][tid],
                      &wt[(((size_t)(ocbase + o)) * CIN + cin) * 9 + k], 4);
        }
    };

    issue_loads(0, 0);
    cp_commit();

    for (int cin = 0; cin < CIN; cin++) {
        const int buf = cin & 1;
        if (cin + 1 < CIN) {
            issue_loads(cin + 1, buf ^ 1);
            cp_commit();
            cp_wait<1>();
        } else {
            cp_wait<0>();
        }
        __syncthreads();

        float v[6][3];
        const int rbase = ty * 4;
#pragma unroll
        for (int r = 0; r < 6; r++)
#pragma unroll
            for (int c = 0; c < 3; c++)
                v[r][c] = sin_[buf][(rbase + r) * 34 + tx + c];

#pragma unroll
        for (int o = 0; o < OCB; o++) {
            float k00 = sw[buf][o*9+0], k01 = sw[buf][o*9+1], k02 = sw[buf][o*9+2];
            float k10 = sw[buf][o*9+3], k11 = sw[buf][o*9+4], k12 = sw[buf][o*9+5];
            float k20 = sw[buf][o*9+6], k21 = sw[buf][o*9+7], k22 = sw[buf][o*9+8];
#pragma unroll
            for (int i = 0; i < 4; i++) {
                acc[o][i] += k00*v[i  ][0] + k01*v[i  ][1] + k02*v[i  ][2]
                           + k10*v[i+1][0] + k11*v[i+1][1] + k12*v[i+1][2]
                           + k20*v[i+2][0] + k21*v[i+2][1] + k22*v[i+2][2];
            }
        }
        __syncthreads();
    }

#pragma unroll
    for (int o = 0; o < OCB; o++) {
        float bv = bias[ocbase + o];
#pragma unroll
        for (int i = 0; i < 4; i++) {
            float r = acc[o][i] + bv;
            if (LRELU) r = (r >= 0.f) ? r : 0.1f * r;
            out[(size_t)(ocbase + o) * HW + (h0 + ty * 4 + i) * Wd + (w0 + tx)] = r;
        }
    }
}

// ---------------- offset/mask transform ----------------
__global__ void offxform_kernel(const float* __restrict__ conv_out,
                                const float* __restrict__ flow,
                                float* __restrict__ off, float* __restrict__ mask)
{
    int idx = blockIdx.x * 256 + threadIdx.x;
    if (idx >= 216 * HW) return;
    int c = idx >> 16;          // idx / HW
    int hw = idx & (HW - 1);
    float v = conv_out[idx];
    if (c < 144) {
        float f = flow[((c & 1) ^ 1) * HW + hw];
        off[idx] = 10.0f * tanhf(v) + f;
    } else {
        mask[(c - 144) * HW + hw] = 1.0f / (1.0f + expf(-v));
    }
}

// ---------------- modulated deformable conv (scalar 8oc x 8px tile) ----------------
// 128 threads, 128 consecutive pixels per block. For each of 8 groups:
// sample the 72-deep (Cg=8 x K=9) columns into smem, then GEMM:
// each thread owns an 8oc x 8px register tile.
__global__ __launch_bounds__(128)
void mdcn_kernel(const float* __restrict__ x, const float* __restrict__ off,
                 const float* __restrict__ mask, const float* __restrict__ wt,
                 const float* __restrict__ bias, float* __restrict__ out)
{
    __shared__ float samp[72 * 128];
    __shared__ float wsm[64 * 73];     // padded stride 73 -> no bank conflict
    const int tid = threadIdx.x;
    const int h = blockIdx.y;
    const int col0 = blockIdx.x * 128;
    const int pix = col0 + tid;        // sampling pixel for this thread
    const int hw = h * Wd + pix;
    const int ob = (tid >> 4) * 8;     // 8 output channels per thread
    const int p0 = (tid & 15) * 8;     // 8 pixels per thread

    float acc[8][8];
#pragma unroll
    for (int o = 0; o < 8; o++)
#pragma unroll
        for (int p = 0; p < 8; p++) acc[o][p] = 0.f;

    for (int g = 0; g < 8; g++) {
        // ---- weight slice for this group: wsm[o][ck], ck = c*9+k ----
        for (int i = tid; i < 64 * 72; i += 128) {
            int o = i / 72, ck = i - o * 72;
            int c = ck / 9, k = ck - c * 9;
            wsm[o * 73 + ck] = wt[((size_t)o * 64 + g * 8 + c) * 9 + k];
        }
        // ---- sampling phase: one pixel per thread, 9 taps x 8 channels ----
#pragma unroll
        for (int k = 0; k < 9; k++) {
            int gk = g * 9 + k;
            float offy = off[(gk * 2 + 0) * HW + hw];
            float offx = off[(gk * 2 + 1) * HW + hw];
            float m    = mask[gk * HW + hw];
            float py = (float)h   + (float)(k / 3 - 1) + offy;
            float px = (float)pix + (float)(k % 3 - 1) + offx;
            float y0f = floorf(py), x0f = floorf(px);
            float ly = py - y0f, lx = px - x0f;
            int y0 = (int)y0f, x0i = (int)x0f;
            int y1 = y0 + 1,  x1 = x0i + 1;
            bool vy0 = (unsigned)y0 < Hd, vy1 = (unsigned)y1 < Hd;
            bool vx0 = (unsigned)x0i < Wd, vx1 = (unsigned)x1 < Wd;
            int yc0 = min(max(y0, 0), Hd - 1), yc1 = min(max(y1, 0), Hd - 1);
            int xc0 = min(max(x0i, 0), Wd - 1), xc1 = min(max(x1, 0), Wd - 1);
            float w00 = (vy0 && vx0) ? (1.f - ly) * (1.f - lx) * m : 0.f;
            float w01 = (vy0 && vx1) ? (1.f - ly) * lx * m : 0.f;
            float w10 = (vy1 && vx0) ? ly * (1.f - lx) * m : 0.f;
            float w11 = (vy1 && vx1) ? ly * lx * m : 0.f;
            int i00 = yc0 * Wd + xc0, i01 = yc0 * Wd + xc1;
            int i10 = yc1 * Wd + xc0, i11 = yc1 * Wd + xc1;
#pragma unroll
            for (int c = 0; c < 8; c++) {
                const float* p = x + (size_t)(g * 8 + c) * HW;
                samp[(c * 9 + k) * 128 + tid] =
                    w00 * p[i00] + w01 * p[i01] + w10 * p[i10] + w11 * p[i11];
            }
        }
        __syncthreads();
        // ---- GEMM: acc[o][p] += W[ob+o, ck] * samp[ck, p0+p] ----
#pragma unroll 2
        for (int ck = 0; ck < 72; ck++) {
            float4 sA = *(const float4*)&samp[ck * 128 + p0];
            float4 sB = *(const float4*)&samp[ck * 128 + p0 + 4];
#pragma unroll
            for (int oi = 0; oi < 8; oi++) {
                float w = wsm[(ob + oi) * 73 + ck];
                acc[oi][0] += w * sA.x;  acc[oi][1] += w * sA.y;
                acc[oi][2] += w * sA.z;  acc[oi][3] += w * sA.w;
                acc[oi][4] += w * sB.x;  acc[oi][5] += w * sB.y;
                acc[oi][6] += w * sB.z;  acc[oi][7] += w * sB.w;
            }
        }
        __syncthreads();
    }

    // ---- epilogue: bias + store (float4 pairs per oc) ----
#pragma unroll
    for (int oi = 0; oi < 8; oi++) {
        float bv = bias[ob + oi];
        float* orow = out + (size_t)(ob + oi) * HW + h * Wd + col0 + p0;
        float4 r0 = make_float4(acc[oi][0] + bv, acc[oi][1] + bv,
                                acc[oi][2] + bv, acc[oi][3] + bv);
        float4 r1 = make_float4(acc[oi][4] + bv, acc[oi][5] + bv,
                                acc[oi][6] + bv, acc[oi][7] + bv);
        *(float4*)(orow)     = r0;
        *(float4*)(orow + 4) = r1;
    }
}

// ---------------- host orchestration ----------------
extern "C" void kernel_launch(void* const* d_in, const int* in_sizes, int n_in,
                              void* d_out, int out_size)
{
    const float* feat_prev       = (const float*)d_in[0];
    const float* feat_next       = (const float*)d_in[1];
    const float* extra_feat_prev = (const float*)d_in[2];
    const float* extra_feat_next = (const float*)d_in[3];
    const float* flow_prev       = (const float*)d_in[4];
    const float* flow_next       = (const float*)d_in[5];
    const float* off1_w[4] = {(const float*)d_in[6],  (const float*)d_in[8],
                              (const float*)d_in[10], (const float*)d_in[12]};
    const float* off1_b[4] = {(const float*)d_in[7],  (const float*)d_in[9],
                              (const float*)d_in[11], (const float*)d_in[13]};
    const float* off2_w[4] = {(const float*)d_in[14], (const float*)d_in[16],
                              (const float*)d_in[18], (const float*)d_in[20]};
    const float* off2_b[4] = {(const float*)d_in[15], (const float*)d_in[17],
                              (const float*)d_in[19], (const float*)d_in[21]};
    const float* dcn1_w = (const float*)d_in[22];
    const float* dcn1_b = (const float*)d_in[23];
    const float* dcn2_w = (const float*)d_in[24];
    const float* dcn2_b = (const float*)d_in[25];
    const float* fus_w  = (const float*)d_in[26];
    const float* fus_b  = (const float*)d_in[27];
    float* out = (float*)d_out;

    float *buf_a, *buf_b, *offp, *maskp, *catp;
    cudaGetSymbolAddress((void**)&buf_a, g_buf_a);
    cudaGetSymbolAddress((void**)&buf_b, g_buf_b);
    cudaGetSymbolAddress((void**)&offp,  g_off);
    cudaGetSymbolAddress((void**)&maskp, g_mask);
    cudaGetSymbolAddress((void**)&catp,  g_cat);

    dim3 cb(32, 8);
    dim3 cg64(8, 8, 4);    // 64 output channels, OCB=16
    dim3 cg216(8, 8, 27);  // 216 output channels, OCB=8
    dim3 mg(2, 256);       // mdcn: 2 x 128 pixels per row, 256 rows
    int nxf = (216 * HW + 255) / 256;

    // ---- branch prev ----
    conv3x3_kernel<128, 16, true ><<<cg64,  cb>>>(extra_feat_prev, off1_w[0], off1_b[0], buf_a);
    conv3x3_kernel< 64, 16, true ><<<cg64,  cb>>>(buf_a, off1_w[1], off1_b[1], buf_b);
    conv3x3_kernel< 64, 16, true ><<<cg64,  cb>>>(buf_b, off1_w[2], off1_b[2], buf_a);
    conv3x3_kernel< 64,  8, false><<<cg216, cb>>>(buf_a, off1_w[3], off1_b[3], buf_b);
    offxform_kernel<<<nxf, 256>>>(buf_b, flow_prev, offp, maskp);
    mdcn_kernel<<<mg, 128>>>(feat_prev, offp, maskp, dcn1_w, dcn1_b, catp);

    // ---- branch next ----
    conv3x3_kernel<128, 16, true ><<<cg64,  cb>>>(extra_feat_next, off2_w[0], off2_b[0], buf_a);
    conv3x3_kernel< 64, 16, true ><<<cg64,  cb>>>(buf_a, off2_w[1], off2_b[1], buf_b);
    conv3x3_kernel< 64, 16, true ><<<cg64,  cb>>>(buf_b, off2_w[2], off2_b[2], buf_a);
    conv3x3_kernel< 64,  8, false><<<cg216, cb>>>(buf_a, off2_w[3], off2_b[3], buf_b);
    offxform_kernel<<<nxf, 256>>>(buf_b, flow_next, offp, maskp);
    mdcn_kernel<<<mg, 128>>>(feat_next, offp, maskp, dcn2_w, dcn2_b, catp + (size_t)64 * HW);

    // ---- fusion conv ----
    conv3x3_kernel<128, 16, false><<<cg64, cb>>>(catp, fus_w, fus_b, out);
}

// round 5
// speedup vs baseline: 2.4498x; 1.0178x over previous
#include <cuda_runtime.h>
#include <cuda_bf16.h>
#include <math.h>

#define Wd 256
#define Hd 256
#define HW 65536

// ---------------- scratch buffers (no allocation allowed) ----------------
__device__ float g_buf_a[216 * HW];
__device__ float g_buf_b[216 * HW];
__device__ float g_off [144 * HW];
__device__ float g_mask[ 72 * HW];
__device__ float g_cat [128 * HW];

// ---------------- cp.async helpers ----------------
__device__ __forceinline__ unsigned smem_u32(const void* p) {
    return (unsigned)__cvta_generic_to_shared(p);
}
__device__ __forceinline__ void cp_async4(void* dst, const void* src, int src_bytes) {
    asm volatile("cp.async.ca.shared.global [%0], [%1], 4, %2;\n"
                 :: "r"(smem_u32(dst)), "l"(src), "r"(src_bytes) : "memory");
}
__device__ __forceinline__ void cp_commit() {
    asm volatile("cp.async.commit_group;\n" ::: "memory");
}
template<int N>
__device__ __forceinline__ void cp_wait() {
    asm volatile("cp.async.wait_group %0;\n" :: "n"(N) : "memory");
}

// ---------------- generic 3x3 conv, pad=1, stride=1 ----------------
// Block (32,8) = 256 threads. Spatial tile 32 wide x 64 tall (8 rows/thread).
// OCB output channels per block (blockIdx.z). Double-buffered cp.async.
// MODE: 0 = leaky-relu, 1 = plain, 2 = fused offset/mask transform
//   (MODE 2: oc<144 -> out = 10*tanh(v)+flow ; oc>=144 -> out2 = sigmoid(v))
#define TILE_E (66 * 34)   // 2244 smem elements per buffer
template<int CIN, int OCB, int MODE>
__global__ __launch_bounds__(256)
void conv3x3_kernel(const float* __restrict__ in, const float* __restrict__ wt,
                    const float* __restrict__ bias, float* __restrict__ out,
                    const float* __restrict__ flow, float* __restrict__ out2)
{
    __shared__ float sin_[2][TILE_E];
    __shared__ float sw[2][OCB * 9];
    const int tx = threadIdx.x, ty = threadIdx.y;
    const int tid = ty * 32 + tx;
    const int w0 = blockIdx.x * 32;
    const int h0 = blockIdx.y * 64;
    const int ocbase = blockIdx.z * OCB;

    // precompute tile-load offsets once (hoisted out of cin loop)
    int ofs[9];
    unsigned vmask = 0;
#pragma unroll
    for (int it = 0; it < 9; it++) {
        int idx = tid + it * 256;
        ofs[it] = 0;
        if (idx < TILE_E) {
            int r = idx / 34, c = idx - r * 34;
            int gh = h0 + r - 1, gw = w0 + c - 1;
            if ((unsigned)gh < Hd && (unsigned)gw < Wd) {
                ofs[it] = gh * Wd + gw;
                vmask |= 1u << it;
            }
        }
    }
    const int wtid_o = tid / 9, wtid_k = tid - wtid_o * 9;  // for weight loads

    float acc[OCB][8];
#pragma unroll
    for (int o = 0; o < OCB; o++)
#pragma unroll
        for (int i = 0; i < 8; i++) acc[o][i] = 0.f;

    auto issue_loads = [&](int cin, int buf) {
        const float* plane = in + (size_t)cin * HW;
#pragma unroll
        for (int it = 0; it < 9; it++) {
            int idx = tid + it * 256;
            if (idx < TILE_E)
                cp_async4(&sin_[buf][idx], plane + ofs[it],
                          (vmask >> it) & 1 ? 4 : 0);
        }
        if (tid < OCB * 9)
            cp_async4(&sw[buf][tid],
                      &wt[(((size_t)(ocbase + wtid_o)) * CIN + cin) * 9 + wtid_k], 4);
    };

    issue_loads(0, 0);
    cp_commit();

    const int rbase = ty * 8;
    for (int cin = 0; cin < CIN; cin++) {
        const int buf = cin & 1;
        if (cin + 1 < CIN) {
            issue_loads(cin + 1, buf ^ 1);
            cp_commit();
            cp_wait<1>();
        } else {
            cp_wait<0>();
        }
        __syncthreads();

        float v[10][3];
#pragma unroll
        for (int r = 0; r < 10; r++)
#pragma unroll
            for (int c = 0; c < 3; c++)
                v[r][c] = sin_[buf][(rbase + r) * 34 + tx + c];

#pragma unroll
        for (int o = 0; o < OCB; o++) {
            float k00 = sw[buf][o*9+0], k01 = sw[buf][o*9+1], k02 = sw[buf][o*9+2];
            float k10 = sw[buf][o*9+3], k11 = sw[buf][o*9+4], k12 = sw[buf][o*9+5];
            float k20 = sw[buf][o*9+6], k21 = sw[buf][o*9+7], k22 = sw[buf][o*9+8];
#pragma unroll
            for (int i = 0; i < 8; i++) {
                acc[o][i] += k00*v[i  ][0] + k01*v[i  ][1] + k02*v[i  ][2]
                           + k10*v[i+1][0] + k11*v[i+1][1] + k12*v[i+1][2]
                           + k20*v[i+2][0] + k21*v[i+2][1] + k22*v[i+2][2];
            }
        }
        __syncthreads();
    }

#pragma unroll
    for (int o = 0; o < OCB; o++) {
        const int oc = ocbase + o;
        float bv = bias[oc];
#pragma unroll
        for (int i = 0; i < 8; i++) {
            float r = acc[o][i] + bv;
            const int row = h0 + rbase + i;
            const int pix = row * Wd + (w0 + tx);
            if (MODE == 0) {
                r = (r >= 0.f) ? r : 0.1f * r;
                out[(size_t)oc * HW + pix] = r;
            } else if (MODE == 1) {
                out[(size_t)oc * HW + pix] = r;
            } else {
                if (oc < 144) {
                    float f = flow[((oc & 1) ^ 1) * HW + pix];
                    out[(size_t)oc * HW + pix] = 10.0f * tanhf(r) + f;
                } else {
                    out2[(size_t)(oc - 144) * HW + pix] = 1.0f / (1.0f + expf(-r));
                }
            }
        }
    }
}

// ---------------- modulated deformable conv (scalar 8oc x 8px tile) ----------------
__global__ __launch_bounds__(128)
void mdcn_kernel(const float* __restrict__ x, const float* __restrict__ off,
                 const float* __restrict__ mask, const float* __restrict__ wt,
                 const float* __restrict__ bias, float* __restrict__ out)
{
    __shared__ float samp[72 * 128];
    __shared__ float wsm[64 * 73];     // padded stride 73 -> no bank conflict
    const int tid = threadIdx.x;
    const int h = blockIdx.y;
    const int col0 = blockIdx.x * 128;
    const int pix = col0 + tid;        // sampling pixel for this thread
    const int hw = h * Wd + pix;
    const int ob = (tid >> 4) * 8;     // 8 output channels per thread
    const int p0 = (tid & 15) * 8;     // 8 pixels per thread

    float acc[8][8];
#pragma unroll
    for (int o = 0; o < 8; o++)
#pragma unroll
        for (int p = 0; p < 8; p++) acc[o][p] = 0.f;

    for (int g = 0; g < 8; g++) {
        // ---- weight slice for this group: wsm[o][ck], ck = c*9+k ----
        for (int i = tid; i < 64 * 72; i += 128) {
            int o = i / 72, ck = i - o * 72;
            int c = ck / 9, k = ck - c * 9;
            wsm[o * 73 + ck] = wt[((size_t)o * 64 + g * 8 + c) * 9 + k];
        }
        // ---- sampling phase: one pixel per thread, 9 taps x 8 channels ----
#pragma unroll
        for (int k = 0; k < 9; k++) {
            int gk = g * 9 + k;
            float offy = off[(gk * 2 + 0) * HW + hw];
            float offx = off[(gk * 2 + 1) * HW + hw];
            float m    = mask[gk * HW + hw];
            float py = (float)h   + (float)(k / 3 - 1) + offy;
            float px = (float)pix + (float)(k % 3 - 1) + offx;
            float y0f = floorf(py), x0f = floorf(px);
            float ly = py - y0f, lx = px - x0f;
            int y0 = (int)y0f, x0i = (int)x0f;
            int y1 = y0 + 1,  x1 = x0i + 1;
            bool vy0 = (unsigned)y0 < Hd, vy1 = (unsigned)y1 < Hd;
            bool vx0 = (unsigned)x0i < Wd, vx1 = (unsigned)x1 < Wd;
            int yc0 = min(max(y0, 0), Hd - 1), yc1 = min(max(y1, 0), Hd - 1);
            int xc0 = min(max(x0i, 0), Wd - 1), xc1 = min(max(x1, 0), Wd - 1);
            float w00 = (vy0 && vx0) ? (1.f - ly) * (1.f - lx) * m : 0.f;
            float w01 = (vy0 && vx1) ? (1.f - ly) * lx * m : 0.f;
            float w10 = (vy1 && vx0) ? ly * (1.f - lx) * m : 0.f;
            float w11 = (vy1 && vx1) ? ly * lx * m : 0.f;
            int i00 = yc0 * Wd + xc0, i01 = yc0 * Wd + xc1;
            int i10 = yc1 * Wd + xc0, i11 = yc1 * Wd + xc1;
#pragma unroll
            for (int c = 0; c < 8; c++) {
                const float* p = x + (size_t)(g * 8 + c) * HW;
                samp[(c * 9 + k) * 128 + tid] =
                    w00 * p[i00] + w01 * p[i01] + w10 * p[i10] + w11 * p[i11];
            }
        }
        __syncthreads();
        // ---- GEMM: acc[o][p] += W[ob+o, ck] * samp[ck, p0+p] ----
#pragma unroll 2
        for (int ck = 0; ck < 72; ck++) {
            float4 sA = *(const float4*)&samp[ck * 128 + p0];
            float4 sB = *(const float4*)&samp[ck * 128 + p0 + 4];
#pragma unroll
            for (int oi = 0; oi < 8; oi++) {
                float w = wsm[(ob + oi) * 73 + ck];
                acc[oi][0] += w * sA.x;  acc[oi][1] += w * sA.y;
                acc[oi][2] += w * sA.z;  acc[oi][3] += w * sA.w;
                acc[oi][4] += w * sB.x;  acc[oi][5] += w * sB.y;
                acc[oi][6] += w * sB.z;  acc[oi][7] += w * sB.w;
            }
        }
        __syncthreads();
    }

    // ---- epilogue: bias + store (float4 pairs per oc) ----
#pragma unroll
    for (int oi = 0; oi < 8; oi++) {
        float bv = bias[ob + oi];
        float* orow = out + (size_t)(ob + oi) * HW + h * Wd + col0 + p0;
        float4 r0 = make_float4(acc[oi][0] + bv, acc[oi][1] + bv,
                                acc[oi][2] + bv, acc[oi][3] + bv);
        float4 r1 = make_float4(acc[oi][4] + bv, acc[oi][5] + bv,
                                acc[oi][6] + bv, acc[oi][7] + bv);
        *(float4*)(orow)     = r0;
        *(float4*)(orow + 4) = r1;
    }
}

// ---------------- host orchestration ----------------
extern "C" void kernel_launch(void* const* d_in, const int* in_sizes, int n_in,
                              void* d_out, int out_size)
{
    const float* feat_prev       = (const float*)d_in[0];
    const float* feat_next       = (const float*)d_in[1];
    const float* extra_feat_prev = (const float*)d_in[2];
    const float* extra_feat_next = (const float*)d_in[3];
    const float* flow_prev       = (const float*)d_in[4];
    const float* flow_next       = (const float*)d_in[5];
    const float* off1_w[4] = {(const float*)d_in[6],  (const float*)d_in[8],
                              (const float*)d_in[10], (const float*)d_in[12]};
    const float* off1_b[4] = {(const float*)d_in[7],  (const float*)d_in[9],
                              (const float*)d_in[11], (const float*)d_in[13]};
    const float* off2_w[4] = {(const float*)d_in[14], (const float*)d_in[16],
                              (const float*)d_in[18], (const float*)d_in[20]};
    const float* off2_b[4] = {(const float*)d_in[15], (const float*)d_in[17],
                              (const float*)d_in[19], (const float*)d_in[21]};
    const float* dcn1_w = (const float*)d_in[22];
    const float* dcn1_b = (const float*)d_in[23];
    const float* dcn2_w = (const float*)d_in[24];
    const float* dcn2_b = (const float*)d_in[25];
    const float* fus_w  = (const float*)d_in[26];
    const float* fus_b  = (const float*)d_in[27];
    float* out = (float*)d_out;

    float *buf_a, *buf_b, *offp, *maskp, *catp;
    cudaGetSymbolAddress((void**)&buf_a, g_buf_a);
    cudaGetSymbolAddress((void**)&buf_b, g_buf_b);
    cudaGetSymbolAddress((void**)&offp,  g_off);
    cudaGetSymbolAddress((void**)&maskp, g_mask);
    cudaGetSymbolAddress((void**)&catp,  g_cat);

    dim3 cb(32, 8);
    dim3 cg64(8, 4, 8);    // 64 output channels, OCB=8, tile 32x64
    dim3 cg216(8, 4, 27);  // 216 output channels, OCB=8
    dim3 mg(2, 256);       // mdcn: 2 x 128 pixels per row, 256 rows

    // ---- branch prev ----
    conv3x3_kernel<128, 8, 0><<<cg64,  cb>>>(extra_feat_prev, off1_w[0], off1_b[0], buf_a, nullptr, nullptr);
    conv3x3_kernel< 64, 8, 0><<<cg64,  cb>>>(buf_a, off1_w[1], off1_b[1], buf_b, nullptr, nullptr);
    conv3x3_kernel< 64, 8, 0><<<cg64,  cb>>>(buf_b, off1_w[2], off1_b[2], buf_a, nullptr, nullptr);
    conv3x3_kernel< 64, 8, 2><<<cg216, cb>>>(buf_a, off1_w[3], off1_b[3], offp, flow_prev, maskp);
    mdcn_kernel<<<mg, 128>>>(feat_prev, offp, maskp, dcn1_w, dcn1_b, catp);

    // ---- branch next ----
    conv3x3_kernel<128, 8, 0><<<cg64,  cb>>>(extra_feat_next, off2_w[0], off2_b[0], buf_a, nullptr, nullptr);
    conv3x3_kernel< 64, 8, 0><<<cg64,  cb>>>(buf_a, off2_w[1], off2_b[1], buf_b, nullptr, nullptr);
    conv3x3_kernel< 64, 8, 0><<<cg64,  cb>>>(buf_b, off2_w[2], off2_b[2], buf_a, nullptr, nullptr);
    conv3x3_kernel< 64, 8, 2><<<cg216, cb>>>(buf_a, off2_w[3], off2_b[3], offp, flow_next, maskp);
    mdcn_kernel<<<mg, 128>>>(feat_next, offp, maskp, dcn2_w, dcn2_b, catp + (size_t)64 * HW);

    // ---- fusion conv ----
    conv3x3_kernel<128, 8, 1><<<cg64, cb>>>(catp, fus_w, fus_b, out, nullptr, nullptr);
}